// round 15
// baseline (speedup 1.0000x reference)
#include <cuda_runtime.h>
#include <cuda_bf16.h>
#include <cstdint>

#define MAXN  8192
#define MAXD  1024
#define BM    128
#define BN    128
#define BK    64             // bf16 elems per chunk = 128B rows
#define TPB   256
#define T8    8
#define TOPN  6
#define NTMAX (MAXN / BN)    // 64 key tiles
#define CAP   24

#define ROWB   144           // smem row stride bytes (128B data + 16B pad)
#define ABUF   18432         // 128 rows * 144B (one matrix, one stage)
#define STAGEB 36864         // A + B per stage
#define NSTAGE 3
#define SM_INV (NSTAGE * STAGEB)        // 110592
#define SMEM_REQ (SM_INV + 512)

// ---------------- device scratch (allocation-free contract) ----------------
__device__ __nv_bfloat16 g_qhi[(size_t)MAXN * MAXD];
__device__ __nv_bfloat16 g_khi[(size_t)MAXN * MAXD];
__device__ float g_inv[MAXN];          // 1/||k||
__device__ float g_qn[MAXN];           // ||q||  (margin scaling)
__device__ float g_candv[(size_t)MAXN * NTMAX * T8];
__device__ int   g_candi[(size_t)MAXN * NTMAX * T8];
__device__ int   g_list[(size_t)MAXN * CAP];
__device__ int   g_lcnt[MAXN];
__device__ int   g_count;

// ---------------- helpers ----------------
__device__ __forceinline__ uint32_t smem_u32(const void* p) {
    uint32_t a;
    asm("{ .reg .u64 t; cvta.to.shared.u64 t, %1; cvt.u32.u64 %0, t; }"
        : "=r"(a) : "l"(p));
    return a;
}
__device__ __forceinline__ void cp_async16(uint32_t dst, const void* src) {
    asm volatile("cp.async.cg.shared.global [%0], [%1], 16;"
                 :: "r"(dst), "l"(src));
}
__device__ __forceinline__ void ldsm4(uint32_t* r, uint32_t addr) {
    asm volatile("ldmatrix.sync.aligned.m8n8.x4.shared.b16 {%0,%1,%2,%3}, [%4];"
                 : "=r"(r[0]), "=r"(r[1]), "=r"(r[2]), "=r"(r[3]) : "r"(addr));
}
__device__ __forceinline__ void mma16816(float* d, const uint32_t* a, const uint32_t* b) {
    asm volatile(
        "mma.sync.aligned.m16n8k16.row.col.f32.bf16.bf16.f32 "
        "{%0,%1,%2,%3}, {%4,%5,%6,%7}, {%8,%9}, {%0,%1,%2,%3};"
        : "+f"(d[0]), "+f"(d[1]), "+f"(d[2]), "+f"(d[3])
        : "r"(a[0]), "r"(a[1]), "r"(a[2]), "r"(a[3]), "r"(b[0]), "r"(b[1]));
}

// Branch-light descending insert (strict >, scan order gives earliest-index ties).
template <int NN>
__device__ __forceinline__ void insN(float v, int idx, float* tv, int* ti) {
    if (v > tv[NN - 1]) {
        bool lt[NN];
        #pragma unroll
        for (int j = 0; j < NN; j++) lt[j] = tv[j] < v;
        #pragma unroll
        for (int j = NN - 1; j > 0; j--)
            if (lt[j - 1]) { tv[j] = tv[j - 1]; ti[j] = ti[j - 1]; }
        #pragma unroll
        for (int j = 0; j < NN; j++) {
            bool put = lt[j] && (j == 0 || !lt[j - 1]);
            if (put) { tv[j] = v; ti[j] = idx; }
        }
    }
}

// ---------------- Kernel A: bf16 casts + norms ----------------
__global__ void prep_kernel(const float* __restrict__ qe, const float* __restrict__ ke,
                            int N, int D) {
    if (blockIdx.x == 0 && threadIdx.x == 0) g_count = 0;
    int warp = threadIdx.x >> 5, lane = threadIdx.x & 31;
    int row = blockIdx.x * 8 + warp;
    if (row >= 2 * N) return;
    bool isk = row >= N;
    int r = isk ? row - N : row;
    const float4* src = (const float4*)((isk ? ke : qe) + (size_t)r * D);
    ushort4* hi = (ushort4*)((isk ? g_khi : g_qhi) + (size_t)r * D);
    float s = 0.f;
    int n4 = D >> 2;
    for (int i = lane; i < n4; i += 32) {
        float4 v = src[i];
        s += v.x * v.x + v.y * v.y + v.z * v.z + v.w * v.w;
        ushort4 h;
        h.x = __bfloat16_as_ushort(__float2bfloat16(v.x));
        h.y = __bfloat16_as_ushort(__float2bfloat16(v.y));
        h.z = __bfloat16_as_ushort(__float2bfloat16(v.z));
        h.w = __bfloat16_as_ushort(__float2bfloat16(v.w));
        hi[i] = h;
    }
    #pragma unroll
    for (int o = 16; o > 0; o >>= 1) s += __shfl_xor_sync(0xffffffffu, s, o);
    if (lane == 0) {
        if (isk) g_inv[r] = 1.0f / fmaxf(sqrtf(s), 1e-12f);
        else     g_qn[r]  = sqrtf(s);
    }
}

// ---------------- Kernel B: bf16 HMMA GEMM (3-stage pipeline) + top-8/tile ----------------
__global__ void __launch_bounds__(TPB, 2) gemm_kernel(int N, int D) {
    extern __shared__ char sm[];
    const int tid = threadIdx.x;
    const int lane = tid & 31, wid = tid >> 5;
    const int wm = wid & 1, wn = wid >> 1;
    const int nt_rt = N / BN;
    const int row0 = ((int)blockIdx.x / nt_rt) * BM;
    const int kb   = (int)blockIdx.x % nt_rt;
    const int col0 = kb * BN;

    float* invs = (float*)(sm + SM_INV);
    if (tid < BN) invs[tid] = g_inv[col0 + tid];

    const uint32_t sbase = smem_u32(sm);

    float d[4][4][4];
    #pragma unroll
    for (int mt = 0; mt < 4; mt++)
        #pragma unroll
        for (int nt = 0; nt < 4; nt++)
            #pragma unroll
            for (int j = 0; j < 4; j++) d[mt][nt][j] = 0.f;

    const int NCH = D / BK;     // 16

    // per-thread ldmatrix base offsets (within a stage)
    const uint32_t a_off = (uint32_t)((wm * 64 + (lane & 15)) * ROWB + (lane >> 4) * 16);
    const uint32_t b_off = (uint32_t)(ABUF + (wn * 32 + (lane & 7) + ((lane >> 4) & 1) * 8) * ROWB
                                      + ((lane >> 3) & 1) * 16);
    // per-thread cp.async (row, seg) assignment
    const int ld_r0  = tid >> 3;          // 0..31 (+32 per i)
    const int ld_seg = tid & 7;

    // ---- prologue: stages 0, 1 ----
    #pragma unroll
    for (int s = 0; s < NSTAGE - 1; s++) {
        int k0 = s * BK;
        uint32_t st = sbase + (uint32_t)s * STAGEB;
        #pragma unroll
        for (int i = 0; i < 4; i++) {
            int r = ld_r0 + i * 32;
            cp_async16(st + r * ROWB + ld_seg * 16,
                       g_qhi + (size_t)(row0 + r) * D + k0 + ld_seg * 8);
            cp_async16(st + ABUF + r * ROWB + ld_seg * 16,
                       g_khi + (size_t)(col0 + r) * D + k0 + ld_seg * 8);
        }
        asm volatile("cp.async.commit_group;");
    }

    int stage = 0;
    #pragma unroll 1
    for (int c = 0; c < NCH; c++) {
        asm volatile("cp.async.wait_group 1;");   // stage c resident (own groups)
        __syncthreads();                          // visible to all; stage c-1 fully consumed

        // issue loads for stage c+2 into the buffer freed at iter c-1
        if (c + NSTAGE - 1 < NCH) {
            int k0 = (c + NSTAGE - 1) * BK;
            int bs = stage + (NSTAGE - 1);
            if (bs >= NSTAGE) bs -= NSTAGE;
            uint32_t st = sbase + (uint32_t)bs * STAGEB;
            #pragma unroll
            for (int i = 0; i < 4; i++) {
                int r = ld_r0 + i * 32;
                cp_async16(st + r * ROWB + ld_seg * 16,
                           g_qhi + (size_t)(row0 + r) * D + k0 + ld_seg * 8);
                cp_async16(st + ABUF + r * ROWB + ld_seg * 16,
                           g_khi + (size_t)(col0 + r) * D + k0 + ld_seg * 8);
            }
        }
        asm volatile("cp.async.commit_group;");   // always commit (possibly empty)

        const uint32_t A = sbase + (uint32_t)stage * STAGEB + a_off;
        const uint32_t B = sbase + (uint32_t)stage * STAGEB + b_off;
        #pragma unroll
        for (int ks = 0; ks < 4; ks++) {
            uint32_t a[4][4], b[2][4];
            #pragma unroll
            for (int mt = 0; mt < 4; mt++)
                ldsm4(a[mt], A + mt * (16 * ROWB) + ks * 32);
            #pragma unroll
            for (int p = 0; p < 2; p++)
                ldsm4(b[p], B + p * (16 * ROWB) + ks * 32);
            #pragma unroll
            for (int mt = 0; mt < 4; mt++) {
                mma16816(d[mt][0], a[mt], &b[0][0]);
                mma16816(d[mt][1], a[mt], &b[0][2]);
                mma16816(d[mt][2], a[mt], &b[1][0]);
                mma16816(d[mt][3], a[mt], &b[1][2]);
            }
        }
        if (++stage == NSTAGE) stage = 0;
    }
    __syncthreads();   // all warps done computing before score overlay

    // ---- epilogue: frags -> smem scores (overlays dead buffers) ----
    float* sc = (float*)sm;
    #pragma unroll
    for (int mt = 0; mt < 4; mt++) {
        int r = wm * 64 + mt * 16 + (lane >> 2);
        #pragma unroll
        for (int nt = 0; nt < 4; nt++) {
            int cc = wn * 32 + nt * 8 + (lane & 3) * 2;
            sc[r * 129 + cc]           = d[mt][nt][0];
            sc[r * 129 + cc + 1]       = d[mt][nt][1];
            sc[(r + 8) * 129 + cc]     = d[mt][nt][2];
            sc[(r + 8) * 129 + cc + 1] = d[mt][nt][3];
        }
    }
    __syncthreads();

    if (tid < BM) {
        float tv[T8];
        int   ti[T8];
        #pragma unroll
        for (int j = 0; j < T8; j++) { tv[j] = -1e30f; ti[j] = -1; }
        const float* rowp = sc + tid * 129;
        for (int i = 0; i < BN; i++) {
            float v = rowp[i] * invs[i];
            insN<T8>(v, col0 + i, tv, ti);
        }
        size_t base = ((size_t)(row0 + tid) * nt_rt + kb) * T8;
        #pragma unroll
        for (int j = 0; j < T8; j++) {
            g_candv[base + j] = tv[j];
            g_candi[base + j] = ti[j];
        }
    }
}

// ---------------- Kernel C: margin select ----------------
__global__ void select_kernel(int N) {
    int row = blockIdx.x * blockDim.x + threadIdx.x;
    if (row >= N) return;
    int nt_rt = N / BN;
    int total = nt_rt * T8;
    const float* cv = g_candv + (size_t)row * total;
    const int*   ci = g_candi + (size_t)row * total;
    float tv[TOPN];
    int   td[TOPN];
    #pragma unroll
    for (int j = 0; j < TOPN; j++) { tv[j] = -1e30f; td[j] = -1; }
    for (int i = 0; i < total; i++) insN<TOPN>(cv[i], i, tv, td);
    float thr = tv[TOPN - 1] - 1e-3f * g_qn[row];
    int cnt = 0;
    for (int i = 0; i < total; i++) {
        if (cv[i] >= thr && ci[i] >= 0) {
            if (cnt < CAP) g_list[(size_t)row * CAP + cnt] = ci[i];
            cnt++;
        }
    }
    g_lcnt[row] = cnt < CAP ? cnt : CAP;
}

// ---------------- Kernel D: exact fp32 rescore + match count ----------------
__global__ void rescore_kernel(const float* __restrict__ qe, const float* __restrict__ ke,
                               const int* __restrict__ qids, const int* __restrict__ kids,
                               const int* __restrict__ dk, int N, int D) {
    int gw = (blockIdx.x * blockDim.x + threadIdx.x) >> 5;
    int lane = threadIdx.x & 31;
    if (gw >= N) return;
    int row = gw;
    const float4* q4 = (const float4*)(qe + (size_t)row * D);
    float4 qv[8];
    #pragma unroll
    for (int i = 0; i < 8; i++) qv[i] = q4[i * 32 + lane];

    int n = g_lcnt[row];
    float tv[TOPN];
    int   ti[TOPN];
    #pragma unroll
    for (int j = 0; j < TOPN; j++) { tv[j] = -1e30f; ti[j] = 0x7fffffff; }

    for (int c = 0; c < n; c++) {
        int idx = g_list[(size_t)row * CAP + c];
        const float4* k4 = (const float4*)(ke + (size_t)idx * D);
        float s = 0.f;
        #pragma unroll
        for (int i = 0; i < 8; i++) {
            float4 kv = k4[i * 32 + lane];
            s += qv[i].x * kv.x + qv[i].y * kv.y + qv[i].z * kv.z + qv[i].w * kv.w;
        }
        #pragma unroll
        for (int o = 16; o > 0; o >>= 1) s += __shfl_xor_sync(0xffffffffu, s, o);
        s *= g_inv[idx];
        bool better = (s > tv[TOPN - 1]) ||
                      (s == tv[TOPN - 1] && idx < ti[TOPN - 1]);
        if (better) {
            int pos = TOPN - 1;
            #pragma unroll
            for (int j = TOPN - 1; j > 0; j--) {
                bool gt = (s > tv[j - 1]) || (s == tv[j - 1] && idx < ti[j - 1]);
                if (gt) { tv[j] = tv[j - 1]; ti[j] = ti[j - 1]; pos = j - 1; }
            }
            tv[pos] = s;
            ti[pos] = idx;
        }
    }

    if (lane == 0) {
        int kk = dk[0];
        if (kk > TOPN - 1) kk = TOPN - 1;
        int qid = qids[row];
        int m = 0;
        for (int j = 1; j <= kk; j++) {
            int idx = ti[j];
            if (idx >= 0 && idx < N && kids[idx] == qid) m++;
        }
        if (m) atomicAdd(&g_count, m);
    }
}

// ---------------- Kernel E: mean ----------------
__global__ void finalize_kernel(float* out, const int* __restrict__ dk, int N) {
    if (blockIdx.x == 0 && threadIdx.x == 0)
        out[0] = (float)g_count / ((float)N * (float)dk[0]);
}

extern "C" void kernel_launch(void* const* d_in, const int* in_sizes, int n_in,
                              void* d_out, int out_size)
{
    const int*   qids = (const int*)d_in[0];
    const int*   kids = (const int*)d_in[1];
    const float* qe   = (const float*)d_in[2];
    const float* ke   = (const float*)d_in[3];
    const int*   dk   = (const int*)d_in[4];
    int N = in_sizes[0];
    int D = in_sizes[2] / N;
    float* out = (float*)d_out;

    (void)cudaFuncSetAttribute(gemm_kernel,
                               cudaFuncAttributeMaxDynamicSharedMemorySize, SMEM_REQ);

    prep_kernel<<<(2 * N + 7) / 8, 256>>>(qe, ke, N, D);
    int grid = (N / BM) * (N / BN);
    gemm_kernel<<<grid, TPB, SMEM_REQ>>>(N, D);
    select_kernel<<<(N + 255) / 256, 256>>>(N);
    rescore_kernel<<<(N * 32 + 255) / 256, 256>>>(qe, ke, qids, kids, dk, N, D);
    finalize_kernel<<<1, 32>>>(out, dk, N);
}

// round 17
// speedup vs baseline: 1.1512x; 1.1512x over previous
#include <cuda_runtime.h>
#include <cuda_bf16.h>
#include <cstdint>

#define MAXN  8192
#define MAXD  1024
#define BM    128
#define BN    128
#define BK    64             // bf16 elems per chunk = 128B rows
#define TPB   256
#define T8    8
#define TOPN  6
#define NTMAX (MAXN / BN)    // 64 key tiles
#define CAP   24

#define ROWB  144            // smem row stride bytes (128B data + 16B pad)
#define ABUF  18432          // 128 * 144
#define AB0   0
#define AB1   ABUF
#define BB0   (2 * ABUF)     // 36864
#define BB1   (3 * ABUF)     // 55296
#define SM_INV 73728
#define SMEM_REQ (SM_INV + 512)

// ---------------- device scratch (allocation-free contract) ----------------
__device__ __nv_bfloat16 g_qhi[(size_t)MAXN * MAXD];
__device__ __nv_bfloat16 g_khi[(size_t)MAXN * MAXD];
__device__ float g_inv[MAXN];          // 1/||k||
__device__ float g_qn[MAXN];           // ||q||  (margin scaling)
__device__ float g_candv[(size_t)MAXN * NTMAX * T8];
__device__ int   g_candi[(size_t)MAXN * NTMAX * T8];
__device__ int   g_list[(size_t)MAXN * CAP];
__device__ int   g_lcnt[MAXN];
__device__ int   g_count;

// ---------------- helpers ----------------
__device__ __forceinline__ uint32_t smem_u32(const void* p) {
    uint32_t a;
    asm("{ .reg .u64 t; cvta.to.shared.u64 t, %1; cvt.u32.u64 %0, t; }"
        : "=r"(a) : "l"(p));
    return a;
}
__device__ __forceinline__ void cp_async16(uint32_t dst, const void* src) {
    asm volatile("cp.async.cg.shared.global [%0], [%1], 16;"
                 :: "r"(dst), "l"(src));
}
__device__ __forceinline__ void ldsm4(uint32_t* r, uint32_t addr) {
    asm volatile("ldmatrix.sync.aligned.m8n8.x4.shared.b16 {%0,%1,%2,%3}, [%4];"
                 : "=r"(r[0]), "=r"(r[1]), "=r"(r[2]), "=r"(r[3]) : "r"(addr));
}
__device__ __forceinline__ void mma16816(float* d, const uint32_t* a, const uint32_t* b) {
    asm volatile(
        "mma.sync.aligned.m16n8k16.row.col.f32.bf16.bf16.f32 "
        "{%0,%1,%2,%3}, {%4,%5,%6,%7}, {%8,%9}, {%0,%1,%2,%3};"
        : "+f"(d[0]), "+f"(d[1]), "+f"(d[2]), "+f"(d[3])
        : "r"(a[0]), "r"(a[1]), "r"(a[2]), "r"(a[3]), "r"(b[0]), "r"(b[1]));
}

// Branch-light descending insert (strict >, scan order gives earliest-index ties).
template <int NN>
__device__ __forceinline__ void insN(float v, int idx, float* tv, int* ti) {
    if (v > tv[NN - 1]) {
        bool lt[NN];
        #pragma unroll
        for (int j = 0; j < NN; j++) lt[j] = tv[j] < v;
        #pragma unroll
        for (int j = NN - 1; j > 0; j--)
            if (lt[j - 1]) { tv[j] = tv[j - 1]; ti[j] = ti[j - 1]; }
        #pragma unroll
        for (int j = 0; j < NN; j++) {
            bool put = lt[j] && (j == 0 || !lt[j - 1]);
            if (put) { tv[j] = v; ti[j] = idx; }
        }
    }
}

// Tie-aware insert for exact rescoring (value desc, idx asc) — order-independent.
__device__ __forceinline__ void ins_tie(float v, int idx, float* tv, int* ti) {
    bool better = (v > tv[TOPN - 1]) || (v == tv[TOPN - 1] && idx < ti[TOPN - 1]);
    if (better) {
        int pos = TOPN - 1;
        #pragma unroll
        for (int j = TOPN - 1; j > 0; j--) {
            bool gt = (v > tv[j - 1]) || (v == tv[j - 1] && idx < ti[j - 1]);
            if (gt) { tv[j] = tv[j - 1]; ti[j] = ti[j - 1]; pos = j - 1; }
        }
        tv[pos] = v;
        ti[pos] = idx;
    }
}

// ---------------- Kernel A: bf16 casts + norms ----------------
__global__ void prep_kernel(const float* __restrict__ qe, const float* __restrict__ ke,
                            int N, int D) {
    if (blockIdx.x == 0 && threadIdx.x == 0) g_count = 0;
    int warp = threadIdx.x >> 5, lane = threadIdx.x & 31;
    int row = blockIdx.x * 8 + warp;
    if (row >= 2 * N) return;
    bool isk = row >= N;
    int r = isk ? row - N : row;
    const float4* src = (const float4*)((isk ? ke : qe) + (size_t)r * D);
    ushort4* hi = (ushort4*)((isk ? g_khi : g_qhi) + (size_t)r * D);
    float s = 0.f;
    int n4 = D >> 2;
    for (int i = lane; i < n4; i += 32) {
        float4 v = src[i];
        s += v.x * v.x + v.y * v.y + v.z * v.z + v.w * v.w;
        ushort4 h;
        h.x = __bfloat16_as_ushort(__float2bfloat16(v.x));
        h.y = __bfloat16_as_ushort(__float2bfloat16(v.y));
        h.z = __bfloat16_as_ushort(__float2bfloat16(v.z));
        h.w = __bfloat16_as_ushort(__float2bfloat16(v.w));
        hi[i] = h;
    }
    #pragma unroll
    for (int o = 16; o > 0; o >>= 1) s += __shfl_xor_sync(0xffffffffu, s, o);
    if (lane == 0) {
        if (isk) g_inv[r] = 1.0f / fmaxf(sqrtf(s), 1e-12f);
        else     g_qn[r]  = sqrtf(s);
    }
}

// ---------------- Kernel B: bf16 HMMA GEMM (2-stage, unrolled x2) + top-8/tile ----------------
// Load chunk starting at global k-offset K0 into A buffer ABOFF / B buffer BBOFF.
#define LOAD_CHUNK(K0, ABOFF, BBOFF)                                            \
    {                                                                           \
        _Pragma("unroll")                                                       \
        for (int i = 0; i < 4; i++) {                                           \
            int r = ld_r0 + i * 32;                                             \
            cp_async16(sbase + (ABOFF) + r * ROWB + ld_seg * 16,                \
                       g_qhi + (size_t)(row0 + r) * D + (K0) + ld_seg * 8);     \
            cp_async16(sbase + (BBOFF) + r * ROWB + ld_seg * 16,                \
                       g_khi + (size_t)(col0 + r) * D + (K0) + ld_seg * 8);     \
        }                                                                       \
    }

#define COMPUTE_CHUNK(ABOFF, BBOFF)                                             \
    {                                                                           \
        const uint32_t A = sbase + (ABOFF) + a_off;                             \
        const uint32_t B = sbase + (BBOFF) + b_off;                             \
        _Pragma("unroll")                                                       \
        for (int ks = 0; ks < 4; ks++) {                                        \
            uint32_t a[4][4], b[2][4];                                          \
            _Pragma("unroll")                                                   \
            for (int mt = 0; mt < 4; mt++)                                      \
                ldsm4(a[mt], A + mt * (16 * ROWB) + ks * 32);                   \
            _Pragma("unroll")                                                   \
            for (int p = 0; p < 2; p++)                                         \
                ldsm4(b[p], B + p * (16 * ROWB) + ks * 32);                     \
            _Pragma("unroll")                                                   \
            for (int mt = 0; mt < 4; mt++) {                                    \
                mma16816(d[mt][0], a[mt], &b[0][0]);                            \
                mma16816(d[mt][1], a[mt], &b[0][2]);                            \
                mma16816(d[mt][2], a[mt], &b[1][0]);                            \
                mma16816(d[mt][3], a[mt], &b[1][2]);                            \
            }                                                                   \
        }                                                                       \
    }

__global__ void __launch_bounds__(TPB, 2) gemm_kernel(int N, int D) {
    extern __shared__ char sm[];
    const int tid = threadIdx.x;
    const int lane = tid & 31, wid = tid >> 5;
    const int wm = wid & 1, wn = wid >> 1;
    const int nt_rt = N / BN;
    const int row0 = ((int)blockIdx.x / nt_rt) * BM;
    const int kb   = (int)blockIdx.x % nt_rt;
    const int col0 = kb * BN;

    float* invs = (float*)(sm + SM_INV);
    if (tid < BN) invs[tid] = g_inv[col0 + tid];

    const uint32_t sbase = smem_u32(sm);

    float d[4][4][4];
    #pragma unroll
    for (int mt = 0; mt < 4; mt++)
        #pragma unroll
        for (int nt = 0; nt < 4; nt++)
            #pragma unroll
            for (int j = 0; j < 4; j++) d[mt][nt][j] = 0.f;

    const int NCH = D / BK;     // 16 (even)

    const uint32_t a_off = (uint32_t)((wm * 64 + (lane & 15)) * ROWB + (lane >> 4) * 16);
    const uint32_t b_off = (uint32_t)((wn * 32 + (lane & 7) + ((lane >> 4) & 1) * 8) * ROWB
                                      + ((lane >> 3) & 1) * 16);
    const int ld_r0  = tid >> 3;
    const int ld_seg = tid & 7;

    // ---- prologue: chunk 0 -> buffer 0 ----
    LOAD_CHUNK(0, AB0, BB0);
    asm volatile("cp.async.commit_group;");

    #pragma unroll 1
    for (int c = 0; c < NCH; c += 2) {
        // --- even chunk: compute buffer 0, prefetch chunk c+1 -> buffer 1 ---
        if (c + 1 < NCH) {
            LOAD_CHUNK((c + 1) * BK, AB1, BB1);
            asm volatile("cp.async.commit_group;");
            asm volatile("cp.async.wait_group 1;");
        } else {
            asm volatile("cp.async.wait_group 0;");
        }
        __syncthreads();
        COMPUTE_CHUNK(AB0, BB0);
        __syncthreads();

        // --- odd chunk: compute buffer 1, prefetch chunk c+2 -> buffer 0 ---
        if (c + 2 < NCH) {
            LOAD_CHUNK((c + 2) * BK, AB0, BB0);
            asm volatile("cp.async.commit_group;");
            asm volatile("cp.async.wait_group 1;");
        } else {
            asm volatile("cp.async.wait_group 0;");
        }
        __syncthreads();
        COMPUTE_CHUNK(AB1, BB1);
        __syncthreads();
    }

    // ---- epilogue: frags -> smem scores (overlays dead buffers) ----
    float* sc = (float*)sm;
    #pragma unroll
    for (int mt = 0; mt < 4; mt++) {
        int r = wm * 64 + mt * 16 + (lane >> 2);
        #pragma unroll
        for (int nt = 0; nt < 4; nt++) {
            int cc = wn * 32 + nt * 8 + (lane & 3) * 2;
            sc[r * 129 + cc]           = d[mt][nt][0];
            sc[r * 129 + cc + 1]       = d[mt][nt][1];
            sc[(r + 8) * 129 + cc]     = d[mt][nt][2];
            sc[(r + 8) * 129 + cc + 1] = d[mt][nt][3];
        }
    }
    __syncthreads();

    if (tid < BM) {
        float tv[T8];
        int   ti[T8];
        #pragma unroll
        for (int j = 0; j < T8; j++) { tv[j] = -1e30f; ti[j] = -1; }
        const float* rowp = sc + tid * 129;
        for (int i = 0; i < BN; i++) {
            float v = rowp[i] * invs[i];
            insN<T8>(v, col0 + i, tv, ti);
        }
        size_t base = ((size_t)(row0 + tid) * nt_rt + kb) * T8;
        #pragma unroll
        for (int j = 0; j < T8; j++) {
            g_candv[base + j] = tv[j];
            g_candi[base + j] = ti[j];
        }
    }
}

// ---------------- Kernel C: margin select ----------------
__global__ void select_kernel(int N) {
    int row = blockIdx.x * blockDim.x + threadIdx.x;
    if (row >= N) return;
    int nt_rt = N / BN;
    int total = nt_rt * T8;
    const float* cv = g_candv + (size_t)row * total;
    const int*   ci = g_candi + (size_t)row * total;
    float tv[TOPN];
    int   td[TOPN];
    #pragma unroll
    for (int j = 0; j < TOPN; j++) { tv[j] = -1e30f; td[j] = -1; }
    for (int i = 0; i < total; i++) insN<TOPN>(cv[i], i, tv, td);
    float thr = tv[TOPN - 1] - 1e-3f * g_qn[row];
    int cnt = 0;
    for (int i = 0; i < total; i++) {
        if (cv[i] >= thr && ci[i] >= 0) {
            if (cnt < CAP) g_list[(size_t)row * CAP + cnt] = ci[i];
            cnt++;
        }
    }
    g_lcnt[row] = cnt < CAP ? cnt : CAP;
}

// ---------------- Kernel D: exact fp32 rescore (paired ILP) + match count ----------------
__global__ void rescore_kernel(const float* __restrict__ qe, const float* __restrict__ ke,
                               const int* __restrict__ qids, const int* __restrict__ kids,
                               const int* __restrict__ dk, int N, int D) {
    int gw = (blockIdx.x * blockDim.x + threadIdx.x) >> 5;
    int lane = threadIdx.x & 31;
    if (gw >= N) return;
    int row = gw;
    const float4* q4 = (const float4*)(qe + (size_t)row * D);
    float4 qv[8];
    #pragma unroll
    for (int i = 0; i < 8; i++) qv[i] = q4[i * 32 + lane];

    int n = g_lcnt[row];
    float tv[TOPN];
    int   ti[TOPN];
    #pragma unroll
    for (int j = 0; j < TOPN; j++) { tv[j] = -1e30f; ti[j] = 0x7fffffff; }

    int c = 0;
    for (; c + 1 < n; c += 2) {
        int i0 = g_list[(size_t)row * CAP + c];
        int i1 = g_list[(size_t)row * CAP + c + 1];
        const float4* k0 = (const float4*)(ke + (size_t)i0 * D);
        const float4* k1 = (const float4*)(ke + (size_t)i1 * D);
        float s0 = 0.f, s1 = 0.f;
        #pragma unroll
        for (int i = 0; i < 8; i++) {
            float4 a = k0[i * 32 + lane];
            float4 b = k1[i * 32 + lane];
            s0 += qv[i].x * a.x + qv[i].y * a.y + qv[i].z * a.z + qv[i].w * a.w;
            s1 += qv[i].x * b.x + qv[i].y * b.y + qv[i].z * b.z + qv[i].w * b.w;
        }
        #pragma unroll
        for (int o = 16; o > 0; o >>= 1) {
            s0 += __shfl_xor_sync(0xffffffffu, s0, o);
            s1 += __shfl_xor_sync(0xffffffffu, s1, o);
        }
        s0 *= g_inv[i0];
        s1 *= g_inv[i1];
        ins_tie(s0, i0, tv, ti);
        ins_tie(s1, i1, tv, ti);
    }
    if (c < n) {
        int i0 = g_list[(size_t)row * CAP + c];
        const float4* k0 = (const float4*)(ke + (size_t)i0 * D);
        float s0 = 0.f;
        #pragma unroll
        for (int i = 0; i < 8; i++) {
            float4 a = k0[i * 32 + lane];
            s0 += qv[i].x * a.x + qv[i].y * a.y + qv[i].z * a.z + qv[i].w * a.w;
        }
        #pragma unroll
        for (int o = 16; o > 0; o >>= 1) s0 += __shfl_xor_sync(0xffffffffu, s0, o);
        s0 *= g_inv[i0];
        ins_tie(s0, i0, tv, ti);
    }

    if (lane == 0) {
        int kk = dk[0];
        if (kk > TOPN - 1) kk = TOPN - 1;
        int qid = qids[row];
        int m = 0;
        for (int j = 1; j <= kk; j++) {
            int idx = ti[j];
            if (idx >= 0 && idx < N && kids[idx] == qid) m++;
        }
        if (m) atomicAdd(&g_count, m);
    }
}

// ---------------- Kernel E: mean ----------------
__global__ void finalize_kernel(float* out, const int* __restrict__ dk, int N) {
    if (blockIdx.x == 0 && threadIdx.x == 0)
        out[0] = (float)g_count / ((float)N * (float)dk[0]);
}

extern "C" void kernel_launch(void* const* d_in, const int* in_sizes, int n_in,
                              void* d_out, int out_size)
{
    const int*   qids = (const int*)d_in[0];
    const int*   kids = (const int*)d_in[1];
    const float* qe   = (const float*)d_in[2];
    const float* ke   = (const float*)d_in[3];
    const int*   dk   = (const int*)d_in[4];
    int N = in_sizes[0];
    int D = in_sizes[2] / N;
    float* out = (float*)d_out;

    (void)cudaFuncSetAttribute(gemm_kernel,
                               cudaFuncAttributeMaxDynamicSharedMemorySize, SMEM_REQ);

    prep_kernel<<<(2 * N + 7) / 8, 256>>>(qe, ke, N, D);
    int grid = (N / BM) * (N / BN);
    gemm_kernel<<<grid, TPB, SMEM_REQ>>>(N, D);
    select_kernel<<<(N + 255) / 256, 256>>>(N);
    rescore_kernel<<<(N * 32 + 255) / 256, 256>>>(qe, ke, qids, kids, dk, N, D);
    finalize_kernel<<<1, 32>>>(out, dk, N);
}